// round 14
// baseline (speedup 1.0000x reference)
#include <cuda_runtime.h>
#include <cuda.h>
#include <cuda_fp16.h>
#include <cstdint>
#include <math.h>

// ---------------- problem dims ----------------
#define NB 16384
#define ND 2048
#define NH 2048
#define NE 6
#define NC 1024
#define NEH 12288       // E*H
// ---------------- tiling ----------------------
#define TM 128
#define TN 256
#define TK 64                      // k halfs per stage = 128 bytes
#define STAGES 4
#define A_BYTES (TM*TK*2)          // 16384
#define B_BYTES (TN*TK*2)          // 32768
#define STAGE_BYTES (A_BYTES + B_BYTES)     // 49152
#define DATA_OFF 1024
#define SMEM_TOTAL (DATA_OFF + STAGES*STAGE_BYTES)   // 197632
#define KITERS 32                  // both GEMMs: 2048/64
#define KSHIFT 5
#define MAXT 40                    // max tiles per persistent CTA
#define MBLK (NB/TM)               // 128 m-blocks per expert

// ---------------- scratch (device globals; no allocation) -----------------
__device__ __half g_xg [(size_t)NE * NB * ND]; // gathered x per expert (fp16)
__device__ __half g_w1h[(size_t)NEH * ND];     // W1 fp16, [E*H, D] K-major
__device__ __half g_w2h[(size_t)NE * NC * NH]; // W2 fp16, native [E,C,H] K-major
__device__ __half g_h  [(size_t)NE * NB * NH]; // compact gw-scaled gelu(xW1+b1)
__device__ __half g_o  [(size_t)NE * NB * NC]; // compact expert outputs (fp16)
__device__ int    g_rows[NE * NB];             // per-expert compacted row lists
__device__ int    g_cnt [NE];
__device__ int    g_idx [NB * 3];              // per row: (e<<14)|i  x3
__device__ int    g_flag[NE * MBLK];           // G1 n-tile completion counters

// ---------------- ptx helpers ----------------------------------------------
__device__ __forceinline__ uint32_t smem_u32(const void* p) {
    uint32_t a;
    asm("{ .reg .u64 t; cvta.to.shared.u64 t, %1; cvt.u32.u64 %0, t; }"
        : "=r"(a) : "l"(p));
    return a;
}

#define LDSM4(r0, r1, r2, r3, addr) \
    asm volatile("ldmatrix.sync.aligned.m8n8.x4.shared.b16 {%0,%1,%2,%3}, [%4];" \
        : "=r"(r0), "=r"(r1), "=r"(r2), "=r"(r3) : "r"((uint32_t)(addr)))

#define MBARRIER_INIT(addr, count) \
    asm volatile("mbarrier.init.shared.b64 [%0], %1;" \
        :: "r"((uint32_t)(addr)), "r"((uint32_t)(count)) : "memory")
#define MBARRIER_EXPECT_TX(addr, bytes) \
    asm volatile("mbarrier.arrive.expect_tx.shared.b64 _, [%0], %1;" \
        :: "r"((uint32_t)(addr)), "r"((uint32_t)(bytes)) : "memory")
#define MBARRIER_ARRIVE(addr) \
    asm volatile("mbarrier.arrive.shared.b64 _, [%0];" \
        :: "r"((uint32_t)(addr)) : "memory")

#define MBARRIER_WAIT_PARITY(mbar_smem_addr, phase_parity) do { \
    uint32_t _mbar = (uint32_t)(mbar_smem_addr); \
    uint32_t _parity = (uint32_t)(phase_parity); \
    uint32_t _done; \
    asm volatile("{\n\t.reg .pred p;\n\t" \
        "mbarrier.try_wait.parity.acquire.cta.shared::cta.b64 p, [%1], %2;\n\t" \
        "selp.b32 %0, 1, 0, p;\n\t}" \
        : "=r"(_done) : "r"(_mbar), "r"(_parity) : "memory"); \
    if (!_done) { \
        asm volatile("{\n\t.reg .pred P1;\n\t" \
            "WAIT_LOOP_%=:\n\t" \
            "mbarrier.try_wait.parity.acquire.cta.shared::cta.b64 P1, [%0], %1, 0x989680;\n\t" \
            "@P1 bra.uni WAIT_DONE_%=;\n\t" \
            "bra.uni WAIT_LOOP_%=;\n\t" \
            "WAIT_DONE_%=:\n\t}" \
            :: "r"(_mbar), "r"(_parity) : "memory"); \
    } \
} while (0)

#define MBARRIER_WAIT_PARITY_RELAXED(mbar_smem_addr, phase_parity) do { \
    uint32_t _mbar = (uint32_t)(mbar_smem_addr); \
    uint32_t _parity = (uint32_t)(phase_parity); \
    uint32_t _done; \
    asm volatile("{\n\t.reg .pred p;\n\t" \
        "mbarrier.try_wait.parity.relaxed.cta.shared::cta.b64 p, [%1], %2, 0x989680;\n\t" \
        "selp.b32 %0, 1, 0, p;\n\t}" \
        : "=r"(_done) : "r"(_mbar), "r"(_parity) : "memory"); \
    if (!_done) { \
        asm volatile("{\n\t.reg .pred P1;\n\t" \
            "WAIT_LOOP_%=:\n\t" \
            "mbarrier.try_wait.parity.relaxed.cta.shared::cta.b64 P1, [%0], %1, 0x989680;\n\t" \
            "@P1 bra.uni WAIT_DONE_%=;\n\t" \
            "bra.uni WAIT_LOOP_%=;\n\t" \
            "WAIT_DONE_%=:\n\t}" \
            :: "r"(_mbar), "r"(_parity) : "memory"); \
    } \
} while (0)

#define TMA2D(smem_addr, map_ptr, cx, cy, mbar) \
    asm volatile("cp.async.bulk.tensor.2d.shared::cta.global.tile.mbarrier::complete_tx::bytes " \
        "[%0], [%1, {%2, %3}], [%4];" \
        :: "r"((uint32_t)(smem_addr)), "l"(map_ptr), "r"((int)(cx)), "r"((int)(cy)), \
           "r"((uint32_t)(mbar)) : "memory")

// m16n8k16 fp16 HMMA, fp32 accumulate, D += A*B
__device__ __forceinline__ void mma_f16(float* d, const uint32_t* a, const uint32_t* b) {
    asm volatile("mma.sync.aligned.m16n8k16.row.col.f32.f16.f16.f32 "
        "{%0,%1,%2,%3}, {%4,%5,%6,%7}, {%8,%9}, {%0,%1,%2,%3};"
        : "+f"(d[0]), "+f"(d[1]), "+f"(d[2]), "+f"(d[3])
        : "r"(a[0]), "r"(a[1]), "r"(a[2]), "r"(a[3]), "r"(b[0]), "r"(b[1]));
}

__device__ __forceinline__ float gelu_exact(float x) {
    return 0.5f * x * (1.f + erff(x * 0.70710678118654752f));
}
__device__ __forceinline__ uint32_t pack_h2(float a, float b) {
    __half2 h = __floats2half2_rn(a, b);
    return *(uint32_t*)&h;
}

// ---------------- small kernels ---------------------------------------------
__global__ void k_zero() {
    int i = blockIdx.x * blockDim.x + threadIdx.x;
    if (i < NE) g_cnt[i] = 0;
    if (i < NE * MBLK) g_flag[i] = 0;
    if (i < NE * NB) g_rows[i] = 0;
}

// combined W1 + W2 fp16 conversion, grid-stride
__global__ void k_cvt(const float4* __restrict__ w1, const float4* __restrict__ w2,
                      int n1, int ntot) {
    int i = blockIdx.x * blockDim.x + threadIdx.x;
    int stride = gridDim.x * blockDim.x;
    for (; i < ntot; i += stride) {
        float4 v;
        uint2* dst;
        if (i < n1) { v = w1[i]; dst = (uint2*)g_w1h + i; }
        else        { v = w2[i - n1]; dst = (uint2*)g_w2h + (i - n1); }
        uint2 r;
        r.x = pack_h2(v.x, v.y);
        r.y = pack_h2(v.z, v.w);
        *dst = r;
    }
}

// gate + fused gather: fp32 logits, top-3 softmax, compaction; row cached as
// fp16 (uint2 x16 = 32 regs) and written into its <=3 expert slots.
__global__ void __launch_bounds__(256) k_gate(
    const float* __restrict__ x, const float* __restrict__ gW,
    const float* __restrict__ gb, float* __restrict__ gwout) {
    int row = blockIdx.x * 8 + (threadIdx.x >> 5);
    int lane = threadIdx.x & 31;
    const float* xr = x + (size_t)row * ND;
    uint2 xh[16];                  // fp16 row cache
    float acc[NE], acc2[NE];
    #pragma unroll
    for (int e = 0; e < NE; e++) { acc[e] = 0.f; acc2[e] = 0.f; }
    #pragma unroll
    for (int j = 0; j < 8; j++) {
        int d = lane * 4 + j * 256;
        float4 xv  = *(const float4*)(xr + d);
        float4 xv2 = *(const float4*)(xr + d + 128);
        xh[2 * j].x     = pack_h2(xv.x, xv.y);
        xh[2 * j].y     = pack_h2(xv.z, xv.w);
        xh[2 * j + 1].x = pack_h2(xv2.x, xv2.y);
        xh[2 * j + 1].y = pack_h2(xv2.z, xv2.w);
        #pragma unroll
        for (int e = 0; e < NE; e++) {
            float4 wv  = *(const float4*)(gW + (size_t)e * ND + d);
            float4 wv2 = *(const float4*)(gW + (size_t)e * ND + d + 128);
            acc[e]  += xv.x  * wv.x  + xv.y  * wv.y  + xv.z  * wv.z  + xv.w  * wv.w;
            acc2[e] += xv2.x * wv2.x + xv2.y * wv2.y + xv2.z * wv2.z + xv2.w * wv2.w;
        }
    }
    #pragma unroll
    for (int e = 0; e < NE; e++) {
        acc[e] += acc2[e];
        #pragma unroll
        for (int o = 16; o > 0; o >>= 1)
            acc[e] += __shfl_xor_sync(0xFFFFFFFF, acc[e], o);
    }
    float l[NE];
    #pragma unroll
    for (int e = 0; e < NE; e++) l[e] = acc[e] + gb[e];
    bool used[NE] = {false, false, false, false, false, false};
    float mx = -3.4e38f;
    for (int t = 0; t < 3; t++) {
        float best = -3.4e38f; int bi = 0;
        #pragma unroll
        for (int e = 0; e < NE; e++)
            if (!used[e] && l[e] > best) { best = l[e]; bi = e; }
        used[bi] = true;
        if (t == 0) mx = best;
    }
    float s = 0.f;
    #pragma unroll
    for (int e = 0; e < NE; e++) if (used[e]) s += expf(l[e] - mx);
    float inv = 1.f / s;
    if (lane < NE)
        gwout[(size_t)row * NE + lane] = used[lane] ? expf(l[lane] - mx) * inv : 0.f;

    int se3 = 0, si0 = 0, si1 = 0, si2 = 0;
    if (lane == 0) {
        int t = 0, si[3] = {0, 0, 0};
        #pragma unroll
        for (int e = 0; e < NE; e++)
            if (used[e]) {
                int i = atomicAdd(&g_cnt[e], 1);
                g_rows[e * NB + i] = row;
                g_idx[row * 3 + t] = (e << 14) | i;
                se3 |= e << (t * 5);
                si[t] = i;
                t++;
            }
        si0 = si[0]; si1 = si[1]; si2 = si[2];
    }
    se3 = __shfl_sync(0xFFFFFFFF, se3, 0);
    si0 = __shfl_sync(0xFFFFFFFF, si0, 0);
    si1 = __shfl_sync(0xFFFFFFFF, si1, 0);
    si2 = __shfl_sync(0xFFFFFFFF, si2, 0);
    int sis[3] = {si0, si1, si2};

    #pragma unroll
    for (int t = 0; t < 3; t++) {
        int e = (se3 >> (t * 5)) & 31;
        __half* dst = g_xg + ((size_t)e * NB + sis[t]) * ND;
        #pragma unroll
        for (int j = 0; j < 16; j++) {
            int d = lane * 4 + (j & 1) * 128 + (j >> 1) * 256;
            *(uint2*)(dst + d) = xh[j];
        }
    }
}

// ---------------- fused persistent GEMM1+GEMM2 -------------------------------
// Global tile space: [G1 tiles (e-major, m, n over NH/TN)] then [G2 tiles].
// G1 epilogue signals g_flag[e][mb]; G2 producer waits for flag==NH/TN.
__global__ void __launch_bounds__(256, 1) k_gemm(
    const __grid_constant__ CUtensorMap mA1,
    const __grid_constant__ CUtensorMap mB1,
    const __grid_constant__ CUtensorMap mA2,
    const __grid_constant__ CUtensorMap mB2,
    const float* __restrict__ b1,
    const float* __restrict__ gw)
{
    extern __shared__ __align__(1024) char smem[];
    const uint32_t sb = smem_u32(smem);
    const int tid  = threadIdx.x;
    const int lane = tid & 31;
    const int wid  = tid >> 5;
    const int wm = wid >> 2, wn = wid & 3;   // 2 x 4 warp grid, 64x64 tiles
    const int g = lane >> 2, t4 = lane & 3;
    const uint32_t FULL0  = sb;
    const uint32_t EMPTY0 = sb + 64;
    const int NTN1 = NH / TN;                // 8
    const int NTN2 = NC / TN;                // 4

    // ---- build this CTA's tile list ----------------------------------------
    int mt[NE];
    int tiles1 = 0, tiles2 = 0;
    #pragma unroll
    for (int e = 0; e < NE; e++) {
        mt[e] = (g_cnt[e] + TM - 1) / TM;
        tiles1 += mt[e] * NTN1;
        tiles2 += mt[e] * NTN2;
    }
    const int T = tiles1 + tiles2;
    int my_e[MAXT], my_m0[MAXT], my_n0[MAXT], my_md[MAXT];
    int nmine = 0;
    for (int t = blockIdx.x; t < T && nmine < MAXT; t += gridDim.x) {
        int md, e = 0, r;
        if (t < tiles1) {
            md = 0; r = t;
            while (r >= mt[e] * NTN1) { r -= mt[e] * NTN1; e++; }
            my_m0[nmine] = (r / NTN1) * TM;
            my_n0[nmine] = (r % NTN1) * TN;
        } else {
            md = 1; r = t - tiles1;
            while (r >= mt[e] * NTN2) { r -= mt[e] * NTN2; e++; }
            my_m0[nmine] = (r / NTN2) * TM;
            my_n0[nmine] = (r % NTN2) * TN;
        }
        my_e[nmine] = e;
        my_md[nmine] = md;
        nmine++;
    }
    const int S = nmine * KITERS;

    // ldmatrix per-lane address components
    const uint32_t aQ = 16u * (lane >> 4);
    uint32_t aRow[4], aSw[4];
    #pragma unroll
    for (int mi = 0; mi < 4; mi++) {
        int r = wm * 64 + mi * 16 + (lane & 15);
        aRow[mi] = (uint32_t)(r * 128);
        aSw[mi]  = (uint32_t)((r & 7) << 4);
    }
    const uint32_t bQ = 16u * ((lane >> 3) & 1);
    uint32_t bRow[4], bSw[4];
    #pragma unroll
    for (int j = 0; j < 4; j++) {
        int n = wn * 64 + j * 16 + (lane & 7) + 8 * ((lane >> 4) & 1);
        bRow[j] = (uint32_t)(n * 128);
        bSw[j]  = (uint32_t)((n & 7) << 4);
    }

    if (tid == 0) {
        #pragma unroll
        for (int s = 0; s < STAGES; s++) {
            MBARRIER_INIT(FULL0  + s * 8, 1);
            MBARRIER_INIT(EMPTY0 + s * 8, 8);
        }
    }
    __syncthreads();
    if (S == 0) return;

    int se = 0, pp = 1;
    #define ISSUE_STEP(s_) do { \
        int pt_ = (s_) >> KSHIFT; \
        int pkt_ = (s_) & (KITERS - 1); \
        int pe_ = my_e[pt_], pm_ = my_m0[pt_], pn_ = my_n0[pt_], pmd_ = my_md[pt_]; \
        if (pmd_ && pkt_ == 0) { \
            int fl_ = pe_ * MBLK + (pm_ >> 7); \
            int v_; \
            do { \
                asm volatile("ld.acquire.gpu.global.b32 %0, [%1];" \
                             : "=r"(v_) : "l"(g_flag + fl_) : "memory"); \
            } while (v_ < NTN1); \
        } \
        MBARRIER_WAIT_PARITY_RELAXED(EMPTY0 + se * 8, pp); \
        uint32_t fb = FULL0 + se * 8; \
        MBARRIER_EXPECT_TX(fb, STAGE_BYTES); \
        uint32_t dst = sb + DATA_OFF + se * STAGE_BYTES; \
        if (!pmd_) { \
            TMA2D(dst,           &mA1, pkt_ * TK, pe_ * NB + pm_, fb); \
            TMA2D(dst + A_BYTES, &mB1, pkt_ * TK, pe_ * NH + pn_, fb); \
        } else { \
            TMA2D(dst,           &mA2, pkt_ * TK, pe_ * NB + pm_, fb); \
            TMA2D(dst + A_BYTES, &mB2, pkt_ * TK, pe_ * NC + pn_, fb); \
        } \
        if (++se == STAGES) { se = 0; pp ^= 1; } \
    } while (0)

    if (tid == 0) {
        int pre = (S < STAGES - 1) ? S : (STAGES - 1);
        for (int i = 0; i < pre; i++) ISSUE_STEP(i);
    }

    float acc[4][8][4];
    int ce = 0, cm0 = 0, cn0 = 0, cmd = 0;
    int sc = 0, pc = 0;

    #define LOADF(buf, kk) do { \
        _Pragma("unroll") \
        for (int mi = 0; mi < 4; mi++) \
            LDSM4(a[buf][mi][0], a[buf][mi][1], a[buf][mi][2], a[buf][mi][3], \
                  aB + aRow[mi] + (((kk) * 32 + aQ) ^ aSw[mi])); \
        _Pragma("unroll") \
        for (int j = 0; j < 4; j++) \
            LDSM4(b[buf][j][0], b[buf][j][1], b[buf][j][2], b[buf][j][3], \
                  bB + bRow[j] + (((kk) * 32 + bQ) ^ bSw[j])); \
    } while (0)

    for (int s = 0; s < S; s++) {
        const int kt = s & (KITERS - 1);
        if (kt == 0) {
            int ct = s >> KSHIFT;
            ce = my_e[ct]; cm0 = my_m0[ct]; cn0 = my_n0[ct]; cmd = my_md[ct];
            #pragma unroll
            for (int mi = 0; mi < 4; mi++)
                #pragma unroll
                for (int ni = 0; ni < 8; ni++)
                    #pragma unroll
                    for (int q = 0; q < 4; q++) acc[mi][ni][q] = 0.f;
        }
        MBARRIER_WAIT_PARITY(FULL0 + sc * 8, pc);
        if (tid == 0 && s + STAGES - 1 < S) ISSUE_STEP(s + STAGES - 1);

        uint32_t aB = sb + DATA_OFF + sc * STAGE_BYTES;
        uint32_t bB = aB + A_BYTES;
        uint32_t a[2][4][4], b[2][4][4];
        LOADF(0, 0);
        #pragma unroll
        for (int kk = 0; kk < 4; kk++) {
            const int cur = kk & 1;
            if (kk < 3) {
                LOADF(cur ^ 1, kk + 1);
            } else if (lane == 0) {
                MBARRIER_ARRIVE(EMPTY0 + sc * 8);   // stage fully read
            }
            #pragma unroll
            for (int mi = 0; mi < 4; mi++)
                #pragma unroll
                for (int ni = 0; ni < 8; ni++)
                    mma_f16(acc[mi][ni], a[cur][mi], &b[cur][ni >> 1][(ni & 1) * 2]);
        }
        if (++sc == STAGES) { sc = 0; pc ^= 1; }

        if (kt == KITERS - 1) {
            if (cmd == 0) {
                #pragma unroll
                for (int mi = 0; mi < 4; mi++) {
                    int i = cm0 + wm * 64 + mi * 16 + g;
                    int gb0 = g_rows[ce * NB + i];
                    int gb1 = g_rows[ce * NB + i + 8];
                    float gw0 = __ldg(&gw[(size_t)gb0 * NE + ce]);
                    float gw1 = __ldg(&gw[(size_t)gb1 * NE + ce]);
                    #pragma unroll
                    for (int ni = 0; ni < 8; ni++) {
                        int c = cn0 + wn * 64 + ni * 8 + t4 * 2;
                        float bb0 = __ldg(&b1[ce * NH + c]);
                        float bb1 = __ldg(&b1[ce * NH + c + 1]);
                        uint32_t p0 = pack_h2(gelu_exact(acc[mi][ni][0] + bb0) * gw0,
                                              gelu_exact(acc[mi][ni][1] + bb1) * gw0);
                        uint32_t p1 = pack_h2(gelu_exact(acc[mi][ni][2] + bb0) * gw1,
                                              gelu_exact(acc[mi][ni][3] + bb1) * gw1);
                        *(uint32_t*)(g_h + ((size_t)ce * NB + i) * NH + c)     = p0;
                        *(uint32_t*)(g_h + ((size_t)ce * NB + i + 8) * NH + c) = p1;
                    }
                }
                __threadfence();
                __syncthreads();
                if (tid == 0) atomicAdd(&g_flag[ce * MBLK + (cm0 >> 7)], 1);
            } else {
                #pragma unroll
                for (int mi = 0; mi < 4; mi++) {
                    int i = cm0 + wm * 64 + mi * 16 + g;
                    #pragma unroll
                    for (int ni = 0; ni < 8; ni++) {
                        int c = cn0 + wn * 64 + ni * 8 + t4 * 2;
                        uint32_t p0 = pack_h2(acc[mi][ni][0], acc[mi][ni][1]);
                        uint32_t p1 = pack_h2(acc[mi][ni][2], acc[mi][ni][3]);
                        *(uint32_t*)(g_o + ((size_t)ce * NB + i) * NC + c)     = p0;
                        *(uint32_t*)(g_o + ((size_t)ce * NB + i + 8) * NC + c) = p1;
                    }
                }
            }
        }
    }
    #undef ISSUE_STEP
    #undef LOADF
}

// ---------------- combine: gather top-3 fp16 expert outputs + bias ----------
__global__ void k_comb(const float* __restrict__ gw, const float* __restrict__ b2,
                       float* __restrict__ out) {
    int b = blockIdx.x;
    int t = threadIdx.x;                       // 256 threads x 4 cols
    const float4* b24 = (const float4*)b2;
    float4 a = make_float4(0.f, 0.f, 0.f, 0.f);
    #pragma unroll
    for (int tt = 0; tt < 3; tt++) {
        int v = g_idx[b * 3 + tt];
        int e = v >> 14, i = v & 16383;
        uint2 s2 = *(const uint2*)(g_o + ((size_t)e * NB + i) * NC + t * 4);
        float2 f0 = __half22float2(*(__half2*)&s2.x);
        float2 f1 = __half22float2(*(__half2*)&s2.y);
        float w = __ldg(&gw[(size_t)b * NE + e]);
        float4 bb = b24[((size_t)e * NC >> 2) + t];
        a.x += f0.x + w * bb.x;
        a.y += f0.y + w * bb.y;
        a.z += f1.x + w * bb.z;
        a.w += f1.y + w * bb.w;
    }
    ((float4*)out)[(size_t)b * (NC / 4) + t] = a;
}

// ---------------- host ------------------------------------------------------
typedef CUresult (*EncFn)(CUtensorMap*, CUtensorMapDataType, cuuint32_t, void*,
                          const cuuint64_t*, const cuuint64_t*, const cuuint32_t*,
                          const cuuint32_t*, CUtensorMapInterleave, CUtensorMapSwizzle,
                          CUtensorMapL2promotion, CUtensorMapFloatOOBfill);

static void make2d_f16(EncFn enc, CUtensorMap* m, void* ptr,
                       uint64_t d0, uint64_t d1, uint32_t b0, uint32_t b1) {
    cuuint64_t dims[2] = {d0, d1};
    cuuint64_t strides[1] = {d0 * 2};
    cuuint32_t box[2] = {b0, b1};
    cuuint32_t es[2] = {1, 1};
    enc(m, CU_TENSOR_MAP_DATA_TYPE_FLOAT16, 2, ptr, dims, strides, box, es,
        CU_TENSOR_MAP_INTERLEAVE_NONE, CU_TENSOR_MAP_SWIZZLE_128B,
        CU_TENSOR_MAP_L2_PROMOTION_L2_128B, CU_TENSOR_MAP_FLOAT_OOB_FILL_NONE);
}

extern "C" void kernel_launch(void* const* d_in, const int* in_sizes, int n_in,
                              void* d_out, int out_size) {
    const float* x  = (const float*)d_in[0];
    const float* gW = (const float*)d_in[1];
    const float* gb = (const float*)d_in[2];
    const float* W1 = (const float*)d_in[3];
    const float* b1 = (const float*)d_in[4];
    const float* W2 = (const float*)d_in[5];
    const float* b2 = (const float*)d_in[6];
    float* out   = (float*)d_out;
    float* gwbuf = out + (size_t)NB * NC;     // gw region of the output tuple

    void *p_xg, *p_w1, *p_w2, *p_h;
    cudaGetSymbolAddress(&p_xg, g_xg);
    cudaGetSymbolAddress(&p_w1, g_w1h);
    cudaGetSymbolAddress(&p_w2, g_w2h);
    cudaGetSymbolAddress(&p_h,  g_h);

    int dev = 0;
    cudaGetDevice(&dev);
    cudaDeviceProp prop;
    cudaGetDeviceProperties(&prop, dev);
    int nsm = prop.multiProcessorCount;

    void* sym = nullptr;
    cudaDriverEntryPointQueryResult qr;
    cudaGetDriverEntryPointByVersion("cuTensorMapEncodeTiled", &sym, 12000,
                                     cudaEnableDefault, &qr);
    EncFn enc = (EncFn)sym;

    CUtensorMap mA1, mB1, mA2, mB2;
    make2d_f16(enc, &mA1, p_xg, ND, (uint64_t)NE*NB, TK, TM);  // x gathered [E*NB, D]
    make2d_f16(enc, &mB1, p_w1, ND, NEH,             TK, TN);  // W1 [E*H, D]
    make2d_f16(enc, &mA2, p_h,  NH, (uint64_t)NE*NB, TK, TM);  // h_c [E*NB, H]
    make2d_f16(enc, &mB2, p_w2, NH, (uint64_t)NE*NC, TK, TN);  // W2 [E*C, H]

    cudaFuncSetAttribute(k_gemm, cudaFuncAttributeMaxDynamicSharedMemorySize, SMEM_TOTAL);

    int n1 = (int)((size_t)NEH * ND / 4);
    int n2 = (int)((size_t)NE * NC * NH / 4);
    k_zero<<<(NE * NB + 255) / 256, 256>>>();
    k_cvt<<<6144, 256>>>((const float4*)W1, (const float4*)W2, n1, n1 + n2);
    k_gate<<<NB / 8, 256>>>(x, gW, gb, gwbuf);

    k_gemm<<<nsm, 256, SMEM_TOTAL>>>(mA1, mB1, mA2, mB2, b1, gwbuf);
    k_comb<<<NB, 256>>>(gwbuf, b2, out);
}

// round 16
// speedup vs baseline: 1.0359x; 1.0359x over previous
#include <cuda_runtime.h>
#include <cuda.h>
#include <cuda_fp16.h>
#include <cstdint>
#include <math.h>

// ---------------- problem dims ----------------
#define NB 16384
#define ND 2048
#define NH 2048
#define NE 6
#define NC 1024
#define NEH 12288       // E*H
// ---------------- tiling ----------------------
#define TM 128
#define TN 256
#define TK 64                      // k halfs per stage = 128 bytes
#define STAGES 4
#define A_BYTES (TM*TK*2)          // 16384
#define B_BYTES (TN*TK*2)          // 32768
#define STAGE_BYTES (A_BYTES + B_BYTES)     // 49152
#define DATA_OFF 1024
#define SMEM_TOTAL (DATA_OFF + STAGES*STAGE_BYTES)   // 197632
#define KITERS 32                  // both GEMMs: 2048/64
#define KSHIFT 5
#define MAXT 40                    // max tiles per persistent CTA

// ---------------- scratch (device globals; no allocation) -----------------
__device__ __half g_xg [(size_t)NE * NB * ND]; // gathered x per expert (fp16)
__device__ __half g_w1h[(size_t)NEH * ND];     // W1 fp16, [E*H, D] K-major
__device__ __half g_w2h[(size_t)NE * NC * NH]; // W2 fp16, native [E,C,H] K-major
__device__ __half g_h  [(size_t)NE * NB * NH]; // compact gw-scaled gelu(xW1+b1)
__device__ __half g_o  [(size_t)NE * NB * NC]; // compact expert outputs (fp16)
__device__ int    g_rows[NE * NB];             // per-expert compacted row lists
__device__ int    g_cnt [NE];
__device__ int    g_idx [NB * 3];              // per row: (e<<14)|i  x3

// ---------------- ptx helpers ----------------------------------------------
__device__ __forceinline__ uint32_t smem_u32(const void* p) {
    uint32_t a;
    asm("{ .reg .u64 t; cvta.to.shared.u64 t, %1; cvt.u32.u64 %0, t; }"
        : "=r"(a) : "l"(p));
    return a;
}

#define LDSM4(r0, r1, r2, r3, addr) \
    asm volatile("ldmatrix.sync.aligned.m8n8.x4.shared.b16 {%0,%1,%2,%3}, [%4];" \
        : "=r"(r0), "=r"(r1), "=r"(r2), "=r"(r3) : "r"((uint32_t)(addr)))

#define MBARRIER_INIT(addr, count) \
    asm volatile("mbarrier.init.shared.b64 [%0], %1;" \
        :: "r"((uint32_t)(addr)), "r"((uint32_t)(count)) : "memory")
#define MBARRIER_EXPECT_TX(addr, bytes) \
    asm volatile("mbarrier.arrive.expect_tx.shared.b64 _, [%0], %1;" \
        :: "r"((uint32_t)(addr)), "r"((uint32_t)(bytes)) : "memory")
#define MBARRIER_ARRIVE(addr) \
    asm volatile("mbarrier.arrive.shared.b64 _, [%0];" \
        :: "r"((uint32_t)(addr)) : "memory")

#define MBARRIER_WAIT_PARITY(mbar_smem_addr, phase_parity) do { \
    uint32_t _mbar = (uint32_t)(mbar_smem_addr); \
    uint32_t _parity = (uint32_t)(phase_parity); \
    uint32_t _done; \
    asm volatile("{\n\t.reg .pred p;\n\t" \
        "mbarrier.try_wait.parity.acquire.cta.shared::cta.b64 p, [%1], %2;\n\t" \
        "selp.b32 %0, 1, 0, p;\n\t}" \
        : "=r"(_done) : "r"(_mbar), "r"(_parity) : "memory"); \
    if (!_done) { \
        asm volatile("{\n\t.reg .pred P1;\n\t" \
            "WAIT_LOOP_%=:\n\t" \
            "mbarrier.try_wait.parity.acquire.cta.shared::cta.b64 P1, [%0], %1, 0x989680;\n\t" \
            "@P1 bra.uni WAIT_DONE_%=;\n\t" \
            "bra.uni WAIT_LOOP_%=;\n\t" \
            "WAIT_DONE_%=:\n\t}" \
            :: "r"(_mbar), "r"(_parity) : "memory"); \
    } \
} while (0)

#define MBARRIER_WAIT_PARITY_RELAXED(mbar_smem_addr, phase_parity) do { \
    uint32_t _mbar = (uint32_t)(mbar_smem_addr); \
    uint32_t _parity = (uint32_t)(phase_parity); \
    uint32_t _done; \
    asm volatile("{\n\t.reg .pred p;\n\t" \
        "mbarrier.try_wait.parity.relaxed.cta.shared::cta.b64 p, [%1], %2, 0x989680;\n\t" \
        "selp.b32 %0, 1, 0, p;\n\t}" \
        : "=r"(_done) : "r"(_mbar), "r"(_parity) : "memory"); \
    if (!_done) { \
        asm volatile("{\n\t.reg .pred P1;\n\t" \
            "WAIT_LOOP_%=:\n\t" \
            "mbarrier.try_wait.parity.relaxed.cta.shared::cta.b64 P1, [%0], %1, 0x989680;\n\t" \
            "@P1 bra.uni WAIT_DONE_%=;\n\t" \
            "bra.uni WAIT_LOOP_%=;\n\t" \
            "WAIT_DONE_%=:\n\t}" \
            :: "r"(_mbar), "r"(_parity) : "memory"); \
    } \
} while (0)

#define TMA2D(smem_addr, map_ptr, cx, cy, mbar) \
    asm volatile("cp.async.bulk.tensor.2d.shared::cta.global.tile.mbarrier::complete_tx::bytes " \
        "[%0], [%1, {%2, %3}], [%4];" \
        :: "r"((uint32_t)(smem_addr)), "l"(map_ptr), "r"((int)(cx)), "r"((int)(cy)), \
           "r"((uint32_t)(mbar)) : "memory")

// m16n8k16 fp16 HMMA, fp32 accumulate, D += A*B
__device__ __forceinline__ void mma_f16(float* d, const uint32_t* a, const uint32_t* b) {
    asm volatile("mma.sync.aligned.m16n8k16.row.col.f32.f16.f16.f32 "
        "{%0,%1,%2,%3}, {%4,%5,%6,%7}, {%8,%9}, {%0,%1,%2,%3};"
        : "+f"(d[0]), "+f"(d[1]), "+f"(d[2]), "+f"(d[3])
        : "r"(a[0]), "r"(a[1]), "r"(a[2]), "r"(a[3]), "r"(b[0]), "r"(b[1]));
}

__device__ __forceinline__ float gelu_exact(float x) {
    return 0.5f * x * (1.f + erff(x * 0.70710678118654752f));
}
__device__ __forceinline__ uint32_t pack_h2(float a, float b) {
    __half2 h = __floats2half2_rn(a, b);
    return *(uint32_t*)&h;
}

// ---------------- small kernels ---------------------------------------------
__global__ void k_zero() {
    int i = blockIdx.x * blockDim.x + threadIdx.x;
    if (i < NE) g_cnt[i] = 0;
    if (i < NE * NB) g_rows[i] = 0;
}

// combined W1 + W2 fp16 conversion, grid-stride
__global__ void k_cvt(const float4* __restrict__ w1, const float4* __restrict__ w2,
                      int n1, int ntot) {
    int i = blockIdx.x * blockDim.x + threadIdx.x;
    int stride = gridDim.x * blockDim.x;
    for (; i < ntot; i += stride) {
        float4 v;
        uint2* dst;
        if (i < n1) { v = w1[i]; dst = (uint2*)g_w1h + i; }
        else        { v = w2[i - n1]; dst = (uint2*)g_w2h + (i - n1); }
        uint2 r;
        r.x = pack_h2(v.x, v.y);
        r.y = pack_h2(v.z, v.w);
        *dst = r;
    }
}

// gate + fused gather: fp32 logits, top-3 softmax, compaction; row cached as
// fp16 (uint2 x16 = 32 regs) and written into its <=3 expert slots.
__global__ void __launch_bounds__(256) k_gate(
    const float* __restrict__ x, const float* __restrict__ gW,
    const float* __restrict__ gb, float* __restrict__ gwout) {
    int row = blockIdx.x * 8 + (threadIdx.x >> 5);
    int lane = threadIdx.x & 31;
    const float* xr = x + (size_t)row * ND;
    uint2 xh[16];                  // fp16 row cache
    float acc[NE], acc2[NE];
    #pragma unroll
    for (int e = 0; e < NE; e++) { acc[e] = 0.f; acc2[e] = 0.f; }
    #pragma unroll
    for (int j = 0; j < 8; j++) {
        int d = lane * 4 + j * 256;
        float4 xv  = *(const float4*)(xr + d);
        float4 xv2 = *(const float4*)(xr + d + 128);
        xh[2 * j].x     = pack_h2(xv.x, xv.y);
        xh[2 * j].y     = pack_h2(xv.z, xv.w);
        xh[2 * j + 1].x = pack_h2(xv2.x, xv2.y);
        xh[2 * j + 1].y = pack_h2(xv2.z, xv2.w);
        #pragma unroll
        for (int e = 0; e < NE; e++) {
            float4 wv  = *(const float4*)(gW + (size_t)e * ND + d);
            float4 wv2 = *(const float4*)(gW + (size_t)e * ND + d + 128);
            acc[e]  += xv.x  * wv.x  + xv.y  * wv.y  + xv.z  * wv.z  + xv.w  * wv.w;
            acc2[e] += xv2.x * wv2.x + xv2.y * wv2.y + xv2.z * wv2.z + xv2.w * wv2.w;
        }
    }
    #pragma unroll
    for (int e = 0; e < NE; e++) {
        acc[e] += acc2[e];
        #pragma unroll
        for (int o = 16; o > 0; o >>= 1)
            acc[e] += __shfl_xor_sync(0xFFFFFFFF, acc[e], o);
    }
    float l[NE];
    #pragma unroll
    for (int e = 0; e < NE; e++) l[e] = acc[e] + gb[e];
    bool used[NE] = {false, false, false, false, false, false};
    float mx = -3.4e38f;
    for (int t = 0; t < 3; t++) {
        float best = -3.4e38f; int bi = 0;
        #pragma unroll
        for (int e = 0; e < NE; e++)
            if (!used[e] && l[e] > best) { best = l[e]; bi = e; }
        used[bi] = true;
        if (t == 0) mx = best;
    }
    float s = 0.f;
    #pragma unroll
    for (int e = 0; e < NE; e++) if (used[e]) s += expf(l[e] - mx);
    float inv = 1.f / s;
    if (lane < NE)
        gwout[(size_t)row * NE + lane] = used[lane] ? expf(l[lane] - mx) * inv : 0.f;

    int se3 = 0, si0 = 0, si1 = 0, si2 = 0;
    if (lane == 0) {
        int t = 0, si[3] = {0, 0, 0};
        #pragma unroll
        for (int e = 0; e < NE; e++)
            if (used[e]) {
                int i = atomicAdd(&g_cnt[e], 1);
                g_rows[e * NB + i] = row;
                g_idx[row * 3 + t] = (e << 14) | i;
                se3 |= e << (t * 5);
                si[t] = i;
                t++;
            }
        si0 = si[0]; si1 = si[1]; si2 = si[2];
    }
    se3 = __shfl_sync(0xFFFFFFFF, se3, 0);
    si0 = __shfl_sync(0xFFFFFFFF, si0, 0);
    si1 = __shfl_sync(0xFFFFFFFF, si1, 0);
    si2 = __shfl_sync(0xFFFFFFFF, si2, 0);
    int sis[3] = {si0, si1, si2};

    #pragma unroll
    for (int t = 0; t < 3; t++) {
        int e = (se3 >> (t * 5)) & 31;
        __half* dst = g_xg + ((size_t)e * NB + sis[t]) * ND;
        #pragma unroll
        for (int j = 0; j < 16; j++) {
            int d = lane * 4 + (j & 1) * 128 + (j >> 1) * 256;
            *(uint2*)(dst + d) = xh[j];
        }
    }
}

// ---------------- persistent GEMM: fp16, 128x256 CTA, 64x64 warp tiles ------
// double-buffered ldmatrix fragments; early empty-arrive after last stage read.
// MODE 0: A=g_xg, B=W1h; epi: +b1, gelu, *gw, fp16 -> g_h
// MODE 1: A=g_h,  B=W2h; epi: fp16 store -> g_o
template <int MODE>
__global__ void __launch_bounds__(256, 1) k_gemm(
    const __grid_constant__ CUtensorMap amap,
    const __grid_constant__ CUtensorMap bmap,
    const float* __restrict__ bias,
    const float* __restrict__ gw,
    __half* __restrict__ outp)
{
    extern __shared__ __align__(1024) char smem[];
    const uint32_t sb = smem_u32(smem);
    const int tid  = threadIdx.x;
    const int lane = tid & 31;
    const int wid  = tid >> 5;
    const int wm = wid >> 2, wn = wid & 3;   // 2 x 4 warp grid, 64x64 tiles
    const int g = lane >> 2, t4 = lane & 3;
    const uint32_t FULL0  = sb;
    const uint32_t EMPTY0 = sb + 64;
    const int NB_DIM = (MODE == 0) ? NH : NC;
    const int NTN    = (MODE == 0) ? (NH / TN) : (NC / TN);

    // ---- build this CTA's tile list (static stride over live tiles) --------
    int mt[NE];
    int tiles_total = 0;
    #pragma unroll
    for (int e = 0; e < NE; e++) {
        mt[e] = (g_cnt[e] + TM - 1) / TM;
        tiles_total += mt[e] * NTN;
    }
    int my_e[MAXT], my_m0[MAXT], my_n0[MAXT];
    int nmine = 0;
    for (int t = blockIdx.x; t < tiles_total && nmine < MAXT; t += gridDim.x) {
        int r = t, e = 0;
        while (r >= mt[e] * NTN) { r -= mt[e] * NTN; e++; }
        my_e[nmine]  = e;
        my_m0[nmine] = (r / NTN) * TM;
        my_n0[nmine] = (r % NTN) * TN;
        nmine++;
    }
    const int S = nmine * KITERS;

    // ldmatrix per-lane address components
    const uint32_t aQ = 16u * (lane >> 4);
    uint32_t aRow[4], aSw[4];
    #pragma unroll
    for (int mi = 0; mi < 4; mi++) {
        int r = wm * 64 + mi * 16 + (lane & 15);
        aRow[mi] = (uint32_t)(r * 128);
        aSw[mi]  = (uint32_t)((r & 7) << 4);
    }
    const uint32_t bQ = 16u * ((lane >> 3) & 1);
    uint32_t bRow[4], bSw[4];
    #pragma unroll
    for (int j = 0; j < 4; j++) {
        int n = wn * 64 + j * 16 + (lane & 7) + 8 * ((lane >> 4) & 1);
        bRow[j] = (uint32_t)(n * 128);
        bSw[j]  = (uint32_t)((n & 7) << 4);
    }

    if (tid == 0) {
        #pragma unroll
        for (int s = 0; s < STAGES; s++) {
            MBARRIER_INIT(FULL0  + s * 8, 1);
            MBARRIER_INIT(EMPTY0 + s * 8, 8);
        }
    }
    __syncthreads();
    if (S == 0) return;

    // producer cursor (ring slot + parity) — phase 1: first STAGES waits pass
    int se = 0, pp = 1;
    #define ISSUE_STEP(s_) do { \
        int pt_ = (s_) >> KSHIFT; \
        int pkt_ = (s_) & (KITERS - 1); \
        int pe_ = my_e[pt_]; \
        MBARRIER_WAIT_PARITY_RELAXED(EMPTY0 + se * 8, pp); \
        uint32_t fb = FULL0 + se * 8; \
        MBARRIER_EXPECT_TX(fb, STAGE_BYTES); \
        uint32_t dst = sb + DATA_OFF + se * STAGE_BYTES; \
        TMA2D(dst,           &amap, pkt_ * TK, pe_ * NB + my_m0[pt_], fb); \
        TMA2D(dst + A_BYTES, &bmap, pkt_ * TK, pe_ * NB_DIM + my_n0[pt_], fb); \
        if (++se == STAGES) { se = 0; pp ^= 1; } \
    } while (0)

    if (tid == 0) {
        int pre = (S < STAGES - 1) ? S : (STAGES - 1);
        for (int i = 0; i < pre; i++) ISSUE_STEP(i);
    }

    float acc[4][8][4];
    int ce = 0, cm0 = 0, cn0 = 0;
    int sc = 0, pc = 0;

    #define LOADF(buf, kk) do { \
        _Pragma("unroll") \
        for (int mi = 0; mi < 4; mi++) \
            LDSM4(a[buf][mi][0], a[buf][mi][1], a[buf][mi][2], a[buf][mi][3], \
                  aB + aRow[mi] + (((kk) * 32 + aQ) ^ aSw[mi])); \
        _Pragma("unroll") \
        for (int j = 0; j < 4; j++) \
            LDSM4(b[buf][j][0], b[buf][j][1], b[buf][j][2], b[buf][j][3], \
                  bB + bRow[j] + (((kk) * 32 + bQ) ^ bSw[j])); \
    } while (0)

    for (int s = 0; s < S; s++) {
        const int kt = s & (KITERS - 1);
        if (kt == 0) {
            int ct = s >> KSHIFT;
            ce = my_e[ct]; cm0 = my_m0[ct]; cn0 = my_n0[ct];
            #pragma unroll
            for (int mi = 0; mi < 4; mi++)
                #pragma unroll
                for (int ni = 0; ni < 8; ni++)
                    #pragma unroll
                    for (int q = 0; q < 4; q++) acc[mi][ni][q] = 0.f;
        }
        MBARRIER_WAIT_PARITY(FULL0 + sc * 8, pc);
        if (tid == 0 && s + STAGES - 1 < S) ISSUE_STEP(s + STAGES - 1);

        uint32_t aB = sb + DATA_OFF + sc * STAGE_BYTES;
        uint32_t bB = aB + A_BYTES;
        uint32_t a[2][4][4], b[2][4][4];
        LOADF(0, 0);
        #pragma unroll
        for (int kk = 0; kk < 4; kk++) {
            const int cur = kk & 1;
            if (kk < 3) {
                LOADF(cur ^ 1, kk + 1);
            } else if (lane == 0) {
                MBARRIER_ARRIVE(EMPTY0 + sc * 8);   // stage fully read
            }
            #pragma unroll
            for (int mi = 0; mi < 4; mi++)
                #pragma unroll
                for (int ni = 0; ni < 8; ni++)
                    mma_f16(acc[mi][ni], a[cur][mi], &b[cur][ni >> 1][(ni & 1) * 2]);
        }
        if (++sc == STAGES) { sc = 0; pc ^= 1; }

        if (kt == KITERS - 1) {
            // -------- epilogue for tile (ce, cm0, cn0) -----------------------
            if (MODE == 0) {
                #pragma unroll
                for (int mi = 0; mi < 4; mi++) {
                    int i = cm0 + wm * 64 + mi * 16 + g;
                    int gb0 = g_rows[ce * NB + i];
                    int gb1 = g_rows[ce * NB + i + 8];
                    float gw0 = __ldg(&gw[(size_t)gb0 * NE + ce]);
                    float gw1 = __ldg(&gw[(size_t)gb1 * NE + ce]);
                    #pragma unroll
                    for (int ni = 0; ni < 8; ni++) {
                        int c = cn0 + wn * 64 + ni * 8 + t4 * 2;
                        float bb0 = __ldg(&bias[ce * NH + c]);
                        float bb1 = __ldg(&bias[ce * NH + c + 1]);
                        uint32_t p0 = pack_h2(gelu_exact(acc[mi][ni][0] + bb0) * gw0,
                                              gelu_exact(acc[mi][ni][1] + bb1) * gw0);
                        uint32_t p1 = pack_h2(gelu_exact(acc[mi][ni][2] + bb0) * gw1,
                                              gelu_exact(acc[mi][ni][3] + bb1) * gw1);
                        *(uint32_t*)(outp + ((size_t)ce * NB + i) * NH + c)     = p0;
                        *(uint32_t*)(outp + ((size_t)ce * NB + i + 8) * NH + c) = p1;
                    }
                }
            } else {
                #pragma unroll
                for (int mi = 0; mi < 4; mi++) {
                    int i = cm0 + wm * 64 + mi * 16 + g;
                    #pragma unroll
                    for (int ni = 0; ni < 8; ni++) {
                        int c = cn0 + wn * 64 + ni * 8 + t4 * 2;
                        uint32_t p0 = pack_h2(acc[mi][ni][0], acc[mi][ni][1]);
                        uint32_t p1 = pack_h2(acc[mi][ni][2], acc[mi][ni][3]);
                        *(uint32_t*)(outp + ((size_t)ce * NB + i) * NC + c)     = p0;
                        *(uint32_t*)(outp + ((size_t)ce * NB + i + 8) * NC + c) = p1;
                    }
                }
            }
        }
    }
    #undef ISSUE_STEP
    #undef LOADF
}

// ---------------- combine: gather top-3 fp16 expert outputs + bias ----------
__global__ void k_comb(const float* __restrict__ gw, const float* __restrict__ b2,
                       float* __restrict__ out) {
    int b = blockIdx.x;
    int t = threadIdx.x;                       // 256 threads x 4 cols
    const float4* b24 = (const float4*)b2;
    float4 a = make_float4(0.f, 0.f, 0.f, 0.f);
    #pragma unroll
    for (int tt = 0; tt < 3; tt++) {
        int v = g_idx[b * 3 + tt];
        int e = v >> 14, i = v & 16383;
        uint2 s2 = *(const uint2*)(g_o + ((size_t)e * NB + i) * NC + t * 4);
        float2 f0 = __half22float2(*(__half2*)&s2.x);
        float2 f1 = __half22float2(*(__half2*)&s2.y);
        float w = __ldg(&gw[(size_t)b * NE + e]);
        float4 bb = b24[((size_t)e * NC >> 2) + t];
        a.x += f0.x + w * bb.x;
        a.y += f0.y + w * bb.y;
        a.z += f1.x + w * bb.z;
        a.w += f1.y + w * bb.w;
    }
    ((float4*)out)[(size_t)b * (NC / 4) + t] = a;
}

// ---------------- host ------------------------------------------------------
typedef CUresult (*EncFn)(CUtensorMap*, CUtensorMapDataType, cuuint32_t, void*,
                          const cuuint64_t*, const cuuint64_t*, const cuuint32_t*,
                          const cuuint32_t*, CUtensorMapInterleave, CUtensorMapSwizzle,
                          CUtensorMapL2promotion, CUtensorMapFloatOOBfill);

static void make2d_f16(EncFn enc, CUtensorMap* m, void* ptr,
                       uint64_t d0, uint64_t d1, uint32_t b0, uint32_t b1) {
    cuuint64_t dims[2] = {d0, d1};
    cuuint64_t strides[1] = {d0 * 2};
    cuuint32_t box[2] = {b0, b1};
    cuuint32_t es[2] = {1, 1};
    enc(m, CU_TENSOR_MAP_DATA_TYPE_FLOAT16, 2, ptr, dims, strides, box, es,
        CU_TENSOR_MAP_INTERLEAVE_NONE, CU_TENSOR_MAP_SWIZZLE_128B,
        CU_TENSOR_MAP_L2_PROMOTION_L2_128B, CU_TENSOR_MAP_FLOAT_OOB_FILL_NONE);
}

extern "C" void kernel_launch(void* const* d_in, const int* in_sizes, int n_in,
                              void* d_out, int out_size) {
    const float* x  = (const float*)d_in[0];
    const float* gW = (const float*)d_in[1];
    const float* gb = (const float*)d_in[2];
    const float* W1 = (const float*)d_in[3];
    const float* b1 = (const float*)d_in[4];
    const float* W2 = (const float*)d_in[5];
    const float* b2 = (const float*)d_in[6];
    float* out   = (float*)d_out;
    float* gwbuf = out + (size_t)NB * NC;     // gw region of the output tuple

    void *p_xg, *p_w1, *p_w2, *p_h, *p_o;
    cudaGetSymbolAddress(&p_xg, g_xg);
    cudaGetSymbolAddress(&p_w1, g_w1h);
    cudaGetSymbolAddress(&p_w2, g_w2h);
    cudaGetSymbolAddress(&p_h,  g_h);
    cudaGetSymbolAddress(&p_o,  g_o);

    int dev = 0;
    cudaGetDevice(&dev);
    cudaDeviceProp prop;
    cudaGetDeviceProperties(&prop, dev);
    int nsm = prop.multiProcessorCount;

    void* sym = nullptr;
    cudaDriverEntryPointQueryResult qr;
    cudaGetDriverEntryPointByVersion("cuTensorMapEncodeTiled", &sym, 12000,
                                     cudaEnableDefault, &qr);
    EncFn enc = (EncFn)sym;

    CUtensorMap mA1, mB1, mA2, mB2;
    make2d_f16(enc, &mA1, p_xg, ND, (uint64_t)NE*NB, TK, TM);  // x gathered [E*NB, D]
    make2d_f16(enc, &mB1, p_w1, ND, NEH,             TK, TN);  // W1 [E*H, D]
    make2d_f16(enc, &mA2, p_h,  NH, (uint64_t)NE*NB, TK, TM);  // h_c [E*NB, H]
    make2d_f16(enc, &mB2, p_w2, NH, (uint64_t)NE*NC, TK, TN);  // W2 [E*C, H]

    cudaFuncSetAttribute(k_gemm<0>, cudaFuncAttributeMaxDynamicSharedMemorySize, SMEM_TOTAL);
    cudaFuncSetAttribute(k_gemm<1>, cudaFuncAttributeMaxDynamicSharedMemorySize, SMEM_TOTAL);

    int n1 = (int)((size_t)NEH * ND / 4);
    int n2 = (int)((size_t)NE * NC * NH / 4);
    k_zero<<<(NE * NB + 255) / 256, 256>>>();
    k_cvt<<<6144, 256>>>((const float4*)W1, (const float4*)W2, n1, n1 + n2);
    k_gate<<<NB / 8, 256>>>(x, gW, gb, gwbuf);

    k_gemm<0><<<nsm, 256, SMEM_TOTAL>>>(mA1, mB1, b1, gwbuf, (__half*)p_h);
    k_gemm<1><<<nsm, 256, SMEM_TOTAL>>>(mA2, mB2, b2, gwbuf, (__half*)p_o);
    k_comb<<<NB, 256>>>(gwbuf, b2, out);
}

// round 17
// speedup vs baseline: 1.0390x; 1.0031x over previous
#include <cuda_runtime.h>
#include <cuda.h>
#include <cuda_fp16.h>
#include <cstdint>
#include <math.h>

// ---------------- problem dims ----------------
#define NB 16384
#define ND 2048
#define NH 2048
#define NE 6
#define NC 1024
#define NEH 12288       // E*H
// ---------------- tiling ----------------------
#define TM 128
#define TN 256
#define TK 64                      // k halfs per stage = 128 bytes
#define STAGES 4
#define A_BYTES (TM*TK*2)          // 16384
#define B_BYTES (TN*TK*2)          // 32768
#define STAGE_BYTES (A_BYTES + B_BYTES)     // 49152
#define DATA_OFF 1024
#define SMEM_TOTAL (DATA_OFF + STAGES*STAGE_BYTES)   // 197632
#define KITERS 32                  // both GEMMs: 2048/64
#define KSHIFT 5
#define MAXT 40                    // max tiles per persistent CTA

// ---------------- scratch (device globals; no allocation) -----------------
__device__ __half g_xg [(size_t)NE * NB * ND]; // gathered x per expert (fp16)
__device__ __half g_w1h[(size_t)NEH * ND];     // W1 fp16, [E*H, D] K-major
__device__ __half g_w2h[(size_t)NE * NC * NH]; // W2 fp16, native [E,C,H] K-major
__device__ __half g_h  [(size_t)NE * NB * NH]; // compact gw-scaled gelu(xW1+b1)
__device__ __half g_o  [(size_t)NE * NB * NC]; // compact expert outputs (fp16)
__device__ int    g_rows[NE * NB];             // per-expert compacted row lists
__device__ int    g_cnt [NE];
__device__ int    g_idx [NB * 3];              // per row: (e<<14)|i  x3

// ---------------- ptx helpers ----------------------------------------------
__device__ __forceinline__ uint32_t smem_u32(const void* p) {
    uint32_t a;
    asm("{ .reg .u64 t; cvta.to.shared.u64 t, %1; cvt.u32.u64 %0, t; }"
        : "=r"(a) : "l"(p));
    return a;
}

#define LDSM4(r0, r1, r2, r3, addr) \
    asm volatile("ldmatrix.sync.aligned.m8n8.x4.shared.b16 {%0,%1,%2,%3}, [%4];" \
        : "=r"(r0), "=r"(r1), "=r"(r2), "=r"(r3) : "r"((uint32_t)(addr)))

#define MBARRIER_INIT(addr, count) \
    asm volatile("mbarrier.init.shared.b64 [%0], %1;" \
        :: "r"((uint32_t)(addr)), "r"((uint32_t)(count)) : "memory")
#define MBARRIER_EXPECT_TX(addr, bytes) \
    asm volatile("mbarrier.arrive.expect_tx.shared.b64 _, [%0], %1;" \
        :: "r"((uint32_t)(addr)), "r"((uint32_t)(bytes)) : "memory")
#define MBARRIER_ARRIVE(addr) \
    asm volatile("mbarrier.arrive.shared.b64 _, [%0];" \
        :: "r"((uint32_t)(addr)) : "memory")

#define MBARRIER_WAIT_PARITY(mbar_smem_addr, phase_parity) do { \
    uint32_t _mbar = (uint32_t)(mbar_smem_addr); \
    uint32_t _parity = (uint32_t)(phase_parity); \
    uint32_t _done; \
    asm volatile("{\n\t.reg .pred p;\n\t" \
        "mbarrier.try_wait.parity.acquire.cta.shared::cta.b64 p, [%1], %2;\n\t" \
        "selp.b32 %0, 1, 0, p;\n\t}" \
        : "=r"(_done) : "r"(_mbar), "r"(_parity) : "memory"); \
    if (!_done) { \
        asm volatile("{\n\t.reg .pred P1;\n\t" \
            "WAIT_LOOP_%=:\n\t" \
            "mbarrier.try_wait.parity.acquire.cta.shared::cta.b64 P1, [%0], %1, 0x989680;\n\t" \
            "@P1 bra.uni WAIT_DONE_%=;\n\t" \
            "bra.uni WAIT_LOOP_%=;\n\t" \
            "WAIT_DONE_%=:\n\t}" \
            :: "r"(_mbar), "r"(_parity) : "memory"); \
    } \
} while (0)

#define MBARRIER_WAIT_PARITY_RELAXED(mbar_smem_addr, phase_parity) do { \
    uint32_t _mbar = (uint32_t)(mbar_smem_addr); \
    uint32_t _parity = (uint32_t)(phase_parity); \
    uint32_t _done; \
    asm volatile("{\n\t.reg .pred p;\n\t" \
        "mbarrier.try_wait.parity.relaxed.cta.shared::cta.b64 p, [%1], %2, 0x989680;\n\t" \
        "selp.b32 %0, 1, 0, p;\n\t}" \
        : "=r"(_done) : "r"(_mbar), "r"(_parity) : "memory"); \
    if (!_done) { \
        asm volatile("{\n\t.reg .pred P1;\n\t" \
            "WAIT_LOOP_%=:\n\t" \
            "mbarrier.try_wait.parity.relaxed.cta.shared::cta.b64 P1, [%0], %1, 0x989680;\n\t" \
            "@P1 bra.uni WAIT_DONE_%=;\n\t" \
            "bra.uni WAIT_LOOP_%=;\n\t" \
            "WAIT_DONE_%=:\n\t}" \
            :: "r"(_mbar), "r"(_parity) : "memory"); \
    } \
} while (0)

#define TMA2D(smem_addr, map_ptr, cx, cy, mbar) \
    asm volatile("cp.async.bulk.tensor.2d.shared::cta.global.tile.mbarrier::complete_tx::bytes " \
        "[%0], [%1, {%2, %3}], [%4];" \
        :: "r"((uint32_t)(smem_addr)), "l"(map_ptr), "r"((int)(cx)), "r"((int)(cy)), \
           "r"((uint32_t)(mbar)) : "memory")

// m16n8k16 fp16 HMMA, fp32 accumulate, D += A*B
__device__ __forceinline__ void mma_f16(float* d, const uint32_t* a, const uint32_t* b) {
    asm volatile("mma.sync.aligned.m16n8k16.row.col.f32.f16.f16.f32 "
        "{%0,%1,%2,%3}, {%4,%5,%6,%7}, {%8,%9}, {%0,%1,%2,%3};"
        : "+f"(d[0]), "+f"(d[1]), "+f"(d[2]), "+f"(d[3])
        : "r"(a[0]), "r"(a[1]), "r"(a[2]), "r"(a[3]), "r"(b[0]), "r"(b[1]));
}

__device__ __forceinline__ float gelu_exact(float x) {
    return 0.5f * x * (1.f + erff(x * 0.70710678118654752f));
}
__device__ __forceinline__ uint32_t pack_h2(float a, float b) {
    __half2 h = __floats2half2_rn(a, b);
    return *(uint32_t*)&h;
}

// ---------------- small kernels ---------------------------------------------
__global__ void k_zero() {
    int i = blockIdx.x * blockDim.x + threadIdx.x;
    if (i < NE) g_cnt[i] = 0;
    if (i < NE * NB) g_rows[i] = 0;
}

// float4 -> fp16x4 conversion, grid-stride
__global__ void k_cvt(const float4* __restrict__ in, uint2* __restrict__ out, int n4) {
    int i = blockIdx.x * blockDim.x + threadIdx.x;
    int stride = gridDim.x * blockDim.x;
    for (; i < n4; i += stride) {
        float4 v = in[i];
        uint2 r;
        r.x = pack_h2(v.x, v.y);
        r.y = pack_h2(v.z, v.w);
        out[i] = r;
    }
}

// gate + fused gather: fp32 logits, top-3 softmax, compaction; row cached as
// fp16 (uint2 x16 = 32 regs) and written into its <=3 expert slots.
__global__ void __launch_bounds__(256) k_gate(
    const float* __restrict__ x, const float* __restrict__ gW,
    const float* __restrict__ gb, float* __restrict__ gwout) {
    int row = blockIdx.x * 8 + (threadIdx.x >> 5);
    int lane = threadIdx.x & 31;
    const float* xr = x + (size_t)row * ND;
    uint2 xh[16];                  // fp16 row cache
    float acc[NE], acc2[NE];
    #pragma unroll
    for (int e = 0; e < NE; e++) { acc[e] = 0.f; acc2[e] = 0.f; }
    #pragma unroll
    for (int j = 0; j < 8; j++) {
        int d = lane * 4 + j * 256;
        float4 xv  = *(const float4*)(xr + d);
        float4 xv2 = *(const float4*)(xr + d + 128);
        xh[2 * j].x     = pack_h2(xv.x, xv.y);
        xh[2 * j].y     = pack_h2(xv.z, xv.w);
        xh[2 * j + 1].x = pack_h2(xv2.x, xv2.y);
        xh[2 * j + 1].y = pack_h2(xv2.z, xv2.w);
        #pragma unroll
        for (int e = 0; e < NE; e++) {
            float4 wv  = *(const float4*)(gW + (size_t)e * ND + d);
            float4 wv2 = *(const float4*)(gW + (size_t)e * ND + d + 128);
            acc[e]  += xv.x  * wv.x  + xv.y  * wv.y  + xv.z  * wv.z  + xv.w  * wv.w;
            acc2[e] += xv2.x * wv2.x + xv2.y * wv2.y + xv2.z * wv2.z + xv2.w * wv2.w;
        }
    }
    #pragma unroll
    for (int e = 0; e < NE; e++) {
        acc[e] += acc2[e];
        #pragma unroll
        for (int o = 16; o > 0; o >>= 1)
            acc[e] += __shfl_xor_sync(0xFFFFFFFF, acc[e], o);
    }
    float l[NE];
    #pragma unroll
    for (int e = 0; e < NE; e++) l[e] = acc[e] + gb[e];
    bool used[NE] = {false, false, false, false, false, false};
    float mx = -3.4e38f;
    for (int t = 0; t < 3; t++) {
        float best = -3.4e38f; int bi = 0;
        #pragma unroll
        for (int e = 0; e < NE; e++)
            if (!used[e] && l[e] > best) { best = l[e]; bi = e; }
        used[bi] = true;
        if (t == 0) mx = best;
    }
    float s = 0.f;
    #pragma unroll
    for (int e = 0; e < NE; e++) if (used[e]) s += expf(l[e] - mx);
    float inv = 1.f / s;
    if (lane < NE)
        gwout[(size_t)row * NE + lane] = used[lane] ? expf(l[lane] - mx) * inv : 0.f;

    int se3 = 0, si0 = 0, si1 = 0, si2 = 0;
    if (lane == 0) {
        int t = 0, si[3] = {0, 0, 0};
        #pragma unroll
        for (int e = 0; e < NE; e++)
            if (used[e]) {
                int i = atomicAdd(&g_cnt[e], 1);
                g_rows[e * NB + i] = row;
                g_idx[row * 3 + t] = (e << 14) | i;
                se3 |= e << (t * 5);
                si[t] = i;
                t++;
            }
        si0 = si[0]; si1 = si[1]; si2 = si[2];
    }
    se3 = __shfl_sync(0xFFFFFFFF, se3, 0);
    si0 = __shfl_sync(0xFFFFFFFF, si0, 0);
    si1 = __shfl_sync(0xFFFFFFFF, si1, 0);
    si2 = __shfl_sync(0xFFFFFFFF, si2, 0);
    int sis[3] = {si0, si1, si2};

    #pragma unroll
    for (int t = 0; t < 3; t++) {
        int e = (se3 >> (t * 5)) & 31;
        __half* dst = g_xg + ((size_t)e * NB + sis[t]) * ND;
        #pragma unroll
        for (int j = 0; j < 16; j++) {
            int d = lane * 4 + (j & 1) * 128 + (j >> 1) * 256;
            *(uint2*)(dst + d) = xh[j];
        }
    }
}

// ---------------- persistent GEMM: fp16, 128x256 CTA, 64x64 warp tiles ------
// double-buffered ldmatrix fragments; early empty-arrive; early TMA issue.
// MODE 0: A=g_xg, B=W1h; epi: +b1, gelu, *gw, fp16 -> g_h
// MODE 1: A=g_h,  B=W2h; epi: fp16 store -> g_o
template <int MODE>
__global__ void __launch_bounds__(256, 1) k_gemm(
    const __grid_constant__ CUtensorMap amap,
    const __grid_constant__ CUtensorMap bmap,
    const float* __restrict__ bias,
    const float* __restrict__ gw,
    __half* __restrict__ outp)
{
    extern __shared__ __align__(1024) char smem[];
    const uint32_t sb = smem_u32(smem);
    const int tid  = threadIdx.x;
    const int lane = tid & 31;
    const int wid  = tid >> 5;
    const int wm = wid >> 2, wn = wid & 3;   // 2 x 4 warp grid, 64x64 tiles
    const int g = lane >> 2, t4 = lane & 3;
    const uint32_t FULL0  = sb;
    const uint32_t EMPTY0 = sb + 64;
    const int NB_DIM = (MODE == 0) ? NH : NC;
    const int NTN    = (MODE == 0) ? (NH / TN) : (NC / TN);

    // ---- build this CTA's tile list (static stride over live tiles) --------
    int mt[NE];
    int tiles_total = 0;
    #pragma unroll
    for (int e = 0; e < NE; e++) {
        mt[e] = (g_cnt[e] + TM - 1) / TM;
        tiles_total += mt[e] * NTN;
    }
    int my_e[MAXT], my_m0[MAXT], my_n0[MAXT];
    int nmine = 0;
    for (int t = blockIdx.x; t < tiles_total && nmine < MAXT; t += gridDim.x) {
        int r = t, e = 0;
        while (r >= mt[e] * NTN) { r -= mt[e] * NTN; e++; }
        my_e[nmine]  = e;
        my_m0[nmine] = (r / NTN) * TM;
        my_n0[nmine] = (r % NTN) * TN;
        nmine++;
    }
    const int S = nmine * KITERS;

    // ldmatrix per-lane address components
    const uint32_t aQ = 16u * (lane >> 4);
    uint32_t aRow[4], aSw[4];
    #pragma unroll
    for (int mi = 0; mi < 4; mi++) {
        int r = wm * 64 + mi * 16 + (lane & 15);
        aRow[mi] = (uint32_t)(r * 128);
        aSw[mi]  = (uint32_t)((r & 7) << 4);
    }
    const uint32_t bQ = 16u * ((lane >> 3) & 1);
    uint32_t bRow[4], bSw[4];
    #pragma unroll
    for (int j = 0; j < 4; j++) {
        int n = wn * 64 + j * 16 + (lane & 7) + 8 * ((lane >> 4) & 1);
        bRow[j] = (uint32_t)(n * 128);
        bSw[j]  = (uint32_t)((n & 7) << 4);
    }

    if (tid == 0) {
        #pragma unroll
        for (int s = 0; s < STAGES; s++) {
            MBARRIER_INIT(FULL0  + s * 8, 1);
            MBARRIER_INIT(EMPTY0 + s * 8, 8);
        }
    }
    __syncthreads();
    if (S == 0) return;

    // producer cursor (ring slot + parity) — phase 1: first STAGES waits pass
    int se = 0, pp = 1;
    #define ISSUE_STEP(s_) do { \
        int pt_ = (s_) >> KSHIFT; \
        int pkt_ = (s_) & (KITERS - 1); \
        int pe_ = my_e[pt_]; \
        MBARRIER_WAIT_PARITY_RELAXED(EMPTY0 + se * 8, pp); \
        uint32_t fb = FULL0 + se * 8; \
        MBARRIER_EXPECT_TX(fb, STAGE_BYTES); \
        uint32_t dst = sb + DATA_OFF + se * STAGE_BYTES; \
        TMA2D(dst,           &amap, pkt_ * TK, pe_ * NB + my_m0[pt_], fb); \
        TMA2D(dst + A_BYTES, &bmap, pkt_ * TK, pe_ * NB_DIM + my_n0[pt_], fb); \
        if (++se == STAGES) { se = 0; pp ^= 1; } \
    } while (0)

    if (tid == 0) {
        int pre = (S < STAGES - 1) ? S : (STAGES - 1);
        for (int i = 0; i < pre; i++) ISSUE_STEP(i);
    }

    float acc[4][8][4];
    int ce = 0, cm0 = 0, cn0 = 0;
    int sc = 0, pc = 0;

    #define LOADF(buf, kk) do { \
        _Pragma("unroll") \
        for (int mi = 0; mi < 4; mi++) \
            LDSM4(a[buf][mi][0], a[buf][mi][1], a[buf][mi][2], a[buf][mi][3], \
                  aB + aRow[mi] + (((kk) * 32 + aQ) ^ aSw[mi])); \
        _Pragma("unroll") \
        for (int j = 0; j < 4; j++) \
            LDSM4(b[buf][j][0], b[buf][j][1], b[buf][j][2], b[buf][j][3], \
                  bB + bRow[j] + (((kk) * 32 + bQ) ^ bSw[j])); \
    } while (0)

    for (int s = 0; s < S; s++) {
        const int kt = s & (KITERS - 1);
        if (kt == 0) {
            int ct = s >> KSHIFT;
            ce = my_e[ct]; cm0 = my_m0[ct]; cn0 = my_n0[ct];
            #pragma unroll
            for (int mi = 0; mi < 4; mi++)
                #pragma unroll
                for (int ni = 0; ni < 8; ni++)
                    #pragma unroll
                    for (int q = 0; q < 4; q++) acc[mi][ni][q] = 0.f;
        }
        // early TMA issue: slot (sc+3)&3's EMPTY arrived during step s-1
        if (tid == 0 && s + STAGES - 1 < S) ISSUE_STEP(s + STAGES - 1);
        MBARRIER_WAIT_PARITY(FULL0 + sc * 8, pc);

        uint32_t aB = sb + DATA_OFF + sc * STAGE_BYTES;
        uint32_t bB = aB + A_BYTES;
        uint32_t a[2][4][4], b[2][4][4];
        LOADF(0, 0);
        #pragma unroll
        for (int kk = 0; kk < 4; kk++) {
            const int cur = kk & 1;
            if (kk < 3) {
                LOADF(cur ^ 1, kk + 1);
            } else if (lane == 0) {
                MBARRIER_ARRIVE(EMPTY0 + sc * 8);   // stage fully read
            }
            #pragma unroll
            for (int mi = 0; mi < 4; mi++)
                #pragma unroll
                for (int ni = 0; ni < 8; ni++)
                    mma_f16(acc[mi][ni], a[cur][mi], &b[cur][ni >> 1][(ni & 1) * 2]);
        }
        if (++sc == STAGES) { sc = 0; pc ^= 1; }

        if (kt == KITERS - 1) {
            // -------- epilogue for tile (ce, cm0, cn0) -----------------------
            if (MODE == 0) {
                #pragma unroll
                for (int mi = 0; mi < 4; mi++) {
                    int i = cm0 + wm * 64 + mi * 16 + g;
                    int gb0 = g_rows[ce * NB + i];
                    int gb1 = g_rows[ce * NB + i + 8];
                    float gw0 = __ldg(&gw[(size_t)gb0 * NE + ce]);
                    float gw1 = __ldg(&gw[(size_t)gb1 * NE + ce]);
                    #pragma unroll
                    for (int ni = 0; ni < 8; ni++) {
                        int c = cn0 + wn * 64 + ni * 8 + t4 * 2;
                        float bb0 = __ldg(&bias[ce * NH + c]);
                        float bb1 = __ldg(&bias[ce * NH + c + 1]);
                        uint32_t p0 = pack_h2(gelu_exact(acc[mi][ni][0] + bb0) * gw0,
                                              gelu_exact(acc[mi][ni][1] + bb1) * gw0);
                        uint32_t p1 = pack_h2(gelu_exact(acc[mi][ni][2] + bb0) * gw1,
                                              gelu_exact(acc[mi][ni][3] + bb1) * gw1);
                        *(uint32_t*)(outp + ((size_t)ce * NB + i) * NH + c)     = p0;
                        *(uint32_t*)(outp + ((size_t)ce * NB + i + 8) * NH + c) = p1;
                    }
                }
            } else {
                #pragma unroll
                for (int mi = 0; mi < 4; mi++) {
                    int i = cm0 + wm * 64 + mi * 16 + g;
                    #pragma unroll
                    for (int ni = 0; ni < 8; ni++) {
                        int c = cn0 + wn * 64 + ni * 8 + t4 * 2;
                        uint32_t p0 = pack_h2(acc[mi][ni][0], acc[mi][ni][1]);
                        uint32_t p1 = pack_h2(acc[mi][ni][2], acc[mi][ni][3]);
                        *(uint32_t*)(outp + ((size_t)ce * NB + i) * NC + c)     = p0;
                        *(uint32_t*)(outp + ((size_t)ce * NB + i + 8) * NC + c) = p1;
                    }
                }
            }
        }
    }
    #undef ISSUE_STEP
    #undef LOADF
}

// ---------------- combine: gather top-3 fp16 expert outputs + bias ----------
__global__ void k_comb(const float* __restrict__ gw, const float* __restrict__ b2,
                       float* __restrict__ out) {
    int b = blockIdx.x;
    int t = threadIdx.x;                       // 256 threads x 4 cols
    const float4* b24 = (const float4*)b2;
    float4 a = make_float4(0.f, 0.f, 0.f, 0.f);
    #pragma unroll
    for (int tt = 0; tt < 3; tt++) {
        int v = g_idx[b * 3 + tt];
        int e = v >> 14, i = v & 16383;
        uint2 s2 = *(const uint2*)(g_o + ((size_t)e * NB + i) * NC + t * 4);
        float2 f0 = __half22float2(*(__half2*)&s2.x);
        float2 f1 = __half22float2(*(__half2*)&s2.y);
        float w = __ldg(&gw[(size_t)b * NE + e]);
        float4 bb = b24[((size_t)e * NC >> 2) + t];
        a.x += f0.x + w * bb.x;
        a.y += f0.y + w * bb.y;
        a.z += f1.x + w * bb.z;
        a.w += f1.y + w * bb.w;
    }
    ((float4*)out)[(size_t)b * (NC / 4) + t] = a;
}

// ---------------- host ------------------------------------------------------
typedef CUresult (*EncFn)(CUtensorMap*, CUtensorMapDataType, cuuint32_t, void*,
                          const cuuint64_t*, const cuuint64_t*, const cuuint32_t*,
                          const cuuint32_t*, CUtensorMapInterleave, CUtensorMapSwizzle,
                          CUtensorMapL2promotion, CUtensorMapFloatOOBfill);

static void make2d_f16(EncFn enc, CUtensorMap* m, void* ptr,
                       uint64_t d0, uint64_t d1, uint32_t b0, uint32_t b1) {
    cuuint64_t dims[2] = {d0, d1};
    cuuint64_t strides[1] = {d0 * 2};
    cuuint32_t box[2] = {b0, b1};
    cuuint32_t es[2] = {1, 1};
    enc(m, CU_TENSOR_MAP_DATA_TYPE_FLOAT16, 2, ptr, dims, strides, box, es,
        CU_TENSOR_MAP_INTERLEAVE_NONE, CU_TENSOR_MAP_SWIZZLE_128B,
        CU_TENSOR_MAP_L2_PROMOTION_L2_128B, CU_TENSOR_MAP_FLOAT_OOB_FILL_NONE);
}

extern "C" void kernel_launch(void* const* d_in, const int* in_sizes, int n_in,
                              void* d_out, int out_size) {
    const float* x  = (const float*)d_in[0];
    const float* gW = (const float*)d_in[1];
    const float* gb = (const float*)d_in[2];
    const float* W1 = (const float*)d_in[3];
    const float* b1 = (const float*)d_in[4];
    const float* W2 = (const float*)d_in[5];
    const float* b2 = (const float*)d_in[6];
    float* out   = (float*)d_out;
    float* gwbuf = out + (size_t)NB * NC;     // gw region of the output tuple

    void *p_xg, *p_w1, *p_w2, *p_h, *p_o;
    cudaGetSymbolAddress(&p_xg, g_xg);
    cudaGetSymbolAddress(&p_w1, g_w1h);
    cudaGetSymbolAddress(&p_w2, g_w2h);
    cudaGetSymbolAddress(&p_h,  g_h);
    cudaGetSymbolAddress(&p_o,  g_o);

    int dev = 0;
    cudaGetDevice(&dev);
    cudaDeviceProp prop;
    cudaGetDeviceProperties(&prop, dev);
    int nsm = prop.multiProcessorCount;

    void* sym = nullptr;
    cudaDriverEntryPointQueryResult qr;
    cudaGetDriverEntryPointByVersion("cuTensorMapEncodeTiled", &sym, 12000,
                                     cudaEnableDefault, &qr);
    EncFn enc = (EncFn)sym;

    CUtensorMap mA1, mB1, mA2, mB2;
    make2d_f16(enc, &mA1, p_xg, ND, (uint64_t)NE*NB, TK, TM);  // x gathered [E*NB, D]
    make2d_f16(enc, &mB1, p_w1, ND, NEH,             TK, TN);  // W1 [E*H, D]
    make2d_f16(enc, &mA2, p_h,  NH, (uint64_t)NE*NB, TK, TM);  // h_c [E*NB, H]
    make2d_f16(enc, &mB2, p_w2, NH, (uint64_t)NE*NC, TK, TN);  // W2 [E*C, H]

    cudaFuncSetAttribute(k_gemm<0>, cudaFuncAttributeMaxDynamicSharedMemorySize, SMEM_TOTAL);
    cudaFuncSetAttribute(k_gemm<1>, cudaFuncAttributeMaxDynamicSharedMemorySize, SMEM_TOTAL);

    // aux stream + events for captured fork-join (created once; no device mem)
    static cudaStream_t s_aux = nullptr;
    static cudaEvent_t e0 = nullptr, eW1 = nullptr, eW2 = nullptr;
    if (s_aux == nullptr) {
        cudaStreamCreateWithFlags(&s_aux, cudaStreamNonBlocking);
        cudaEventCreateWithFlags(&e0,  cudaEventDisableTiming);
        cudaEventCreateWithFlags(&eW1, cudaEventDisableTiming);
        cudaEventCreateWithFlags(&eW2, cudaEventDisableTiming);
    }

    int n1 = (int)((size_t)NEH * ND / 4);
    int n2 = (int)((size_t)NE * NC * NH / 4);

    // fork aux branch: W1 convert || {zero, gate};  W2 convert || GEMM1
    cudaEventRecord(e0, 0);
    cudaStreamWaitEvent(s_aux, e0, 0);
    k_cvt<<<4096, 256, 0, s_aux>>>((const float4*)W1, (uint2*)p_w1, n1);
    cudaEventRecord(eW1, s_aux);
    k_cvt<<<4096, 256, 0, s_aux>>>((const float4*)W2, (uint2*)p_w2, n2);
    cudaEventRecord(eW2, s_aux);

    k_zero<<<(NE * NB + 255) / 256, 256>>>();
    k_gate<<<NB / 8, 256>>>(x, gW, gb, gwbuf);

    cudaStreamWaitEvent(0, eW1, 0);
    k_gemm<0><<<nsm, 256, SMEM_TOTAL>>>(mA1, mB1, b1, gwbuf, (__half*)p_h);
    cudaStreamWaitEvent(0, eW2, 0);
    k_gemm<1><<<nsm, 256, SMEM_TOTAL>>>(mA2, mB2, b2, gwbuf, (__half*)p_o);
    k_comb<<<NB, 256>>>(gwbuf, b2, out);
}